// round 13
// baseline (speedup 1.0000x reference)
#include <cuda_runtime.h>
#include <math.h>

// Problem constants (fixed by reference)
#define IMG_W 128
#define IMG_H 128
#define TILE  16              // 16x16 tiles -> 8*8*B = 128 blocks (single wave)
#define PIX   256             // pixels per tile
#define SPLIT 4               // gaussian-axis interleave in accumulate
#define NT    1024            // threads per block
#define CHUNK 1024            // gaussians per chunk (1 per thread)
#define NWARP (NT / 32)       // 32

// ---- packed f32x2 helpers (Blackwell) ----
__device__ __forceinline__ unsigned long long px2(float lo, float hi) {
    unsigned long long d;
    asm("mov.b64 %0, {%1, %2};" : "=l"(d) : "f"(lo), "f"(hi));
    return d;
}
__device__ __forceinline__ void upx2(float& lo, float& hi, unsigned long long v) {
    asm("mov.b64 {%0, %1}, %2;" : "=f"(lo), "=f"(hi) : "l"(v));
}
__device__ __forceinline__ unsigned long long add2(unsigned long long a, unsigned long long b) {
    unsigned long long d;
    asm("add.rn.f32x2 %0, %1, %2;" : "=l"(d) : "l"(a), "l"(b));
    return d;
}
__device__ __forceinline__ unsigned long long fma2(unsigned long long a, unsigned long long b, unsigned long long c) {
    unsigned long long d;
    asm("fma.rn.f32x2 %0, %1, %2, %3;" : "=l"(d) : "l"(a), "l"(b), "l"(c));
    return d;
}

// Fully fused, pipelined; R11 layout + packed accumulators.
__global__ void __launch_bounds__(NT)
fused_kernel(float* __restrict__ out,
             const float* __restrict__ pos,
             const float* __restrict__ col,
             const float* __restrict__ opa,
             const float* __restrict__ sca,
             const float* __restrict__ qv,
             const float* __restrict__ tv,
             int N) {
    __shared__ float4 sP1[CHUNK];     // {-projx, -projy, K2, log2(op)} ; reused as sAcc
    __shared__ float4 sP2[CHUNK];     // {r, g, b, 1}
    __shared__ int    sWCnt[NWARP];   // per-warp survivor counts

    const int t    = threadIdx.x;
    const int lane = t & 31;
    const int wid  = t >> 5;          // 0..31
    const int sub  = wid >> 3;        // 0..3 : accumulate slice
    const int pt   = t & (PIX - 1);   // pixel 0..255
    const int b    = blockIdx.z;
    const int x0   = blockIdx.x * TILE;
    const int y0   = blockIdx.y * TILE;
    const float xf = (float)(x0 + (pt & (TILE - 1)));
    const float yf = (float)(y0 + (pt >> 4));
    const unsigned long long xyp = px2(xf, yf);    // pixel (x, y) pair

    const float fx0 = (float)x0, fx1 = (float)(x0 + TILE - 1);
    const float fy0 = (float)y0, fy1 = (float)(y0 + TILE - 1);

    // Camera for this batch; fold the 500/64 projection constants into rows.
    float qw = qv[b * 4 + 0], qx = qv[b * 4 + 1], qy = qv[b * 4 + 2], qz = qv[b * 4 + 3];
    float inv = rsqrtf(qw * qw + qx * qx + qy * qy + qz * qz);
    qw *= inv; qx *= inv; qy *= inv; qz *= inv;
    const float R00 = 1.f - 2.f * (qy * qy + qz * qz), R01 = 2.f * (qx * qy - qz * qw), R02 = 2.f * (qx * qz + qy * qw);
    const float R10 = 2.f * (qx * qy + qz * qw), R11 = 1.f - 2.f * (qx * qx + qz * qz), R12 = 2.f * (qy * qz - qx * qw);
    const float R20 = 2.f * (qx * qz - qy * qw), R21 = 2.f * (qy * qz + qx * qw), R22 = 1.f - 2.f * (qx * qx + qy * qy);
    const float tx = tv[b * 3 + 0], ty = tv[b * 3 + 1], tz = tv[b * 3 + 2];
    // projx = (cx/cz)*500 + 64 = ((500*R0 + 64*R2)·p + (500*tx + 64*tz)) / cz
    const float A00 = fmaf(500.f, R00, 64.f * R20), A01 = fmaf(500.f, R01, 64.f * R21), A02 = fmaf(500.f, R02, 64.f * R22);
    const float A10 = fmaf(500.f, R10, 64.f * R20), A11 = fmaf(500.f, R11, 64.f * R21), A12 = fmaf(500.f, R12, 64.f * R22);
    const float Atx = fmaf(500.f, tx, 64.f * tz),   Aty = fmaf(500.f, ty, 64.f * tz);

    unsigned long long accRG = 0ull, accBD = 0ull;

    // ---- Prologue: load chunk 0 inputs (8 independent LDGs) ----
    float cPx = 0.f, cPy = 0.f, cPz = 0.f, cSc = 1.f, cOp = 1e-30f;
    float cCr = 0.f, cCg = 0.f, cCb = 0.f;
    if (t < N) {
        cPx = pos[t * 3 + 0]; cPy = pos[t * 3 + 1]; cPz = pos[t * 3 + 2];
        cSc = sca[t]; cOp = opa[t];
        cCr = col[t * 3 + 0]; cCg = col[t * 3 + 1]; cCb = col[t * 3 + 2];
    }

    for (int base = 0; base < N; base += CHUNK) {
        const bool valid = (base + t) < N;

        // ---- Phase 1: project + cull (folded constants; tight bound incl. lo) ----
        float czm = R20 * cPx + R21 * cPy + R22 * cPz + tz;
        float iz  = __fdividef(1.0f, czm);
        float projx = (A00 * cPx + A01 * cPy + A02 * cPz + Atx) * iz;
        float projy = (A10 * cPx + A11 * cPy + A12 * cPz + Aty) * iz;
        float K2 = __fdividef(-0.72134752044f, cSc * cSc);   // -1/(2 var ln2)
        float lo = log2f(fmaxf(cOp, 1e-30f));

        float dx = fmaxf(0.f, fmaxf(fx0 - projx, projx - fx1));
        float dy = fmaxf(0.f, fmaxf(fy0 - projy, projy - fy1));
        float amax = fmaf(K2, fmaf(dx, dx, dy * dy), lo);
        bool keepIt = valid && (amax > -60.f);               // NaN fails -> culled
        float svCr = cCr, svCg = cCg, svCb = cCb;

        // ---- Prefetch next chunk (drains behind compaction + accumulate) ----
        {
            int g = base + CHUNK + t;
            if (g < N) {
                cPx = pos[g * 3 + 0]; cPy = pos[g * 3 + 1]; cPz = pos[g * 3 + 2];
                cSc = sca[g]; cOp = opa[g];
                cCr = col[g * 3 + 0]; cCg = col[g * 3 + 1]; cCb = col[g * 3 + 2];
            }
        }

        // ---- Phase 2: ballot; counts to shared; barrier doubles as reuse guard ----
        unsigned m = __ballot_sync(0xffffffffu, keepIt);
        int myOff = __popc(m & ((1u << lane) - 1u));
        if (lane == 0) sWCnt[wid] = __popc(m);
        __syncthreads();

        // ---- Phase 3: every warp scans the 32 counts; vectorized survivor store ----
        int cvec = sWCnt[lane];
        int incl = cvec;
        #pragma unroll
        for (int o = 1; o < 32; o <<= 1) {
            int v = __shfl_up_sync(0xffffffffu, incl, o);
            if (lane >= o) incl += v;
        }
        int warpBase = __shfl_sync(0xffffffffu, incl - cvec, wid);
        int cnt      = __shfl_sync(0xffffffffu, incl, 31);

        if (keepIt) {
            int wpos = warpBase + myOff;
            sP1[wpos] = make_float4(-projx, -projy, K2, lo);   // negated center
            sP2[wpos] = make_float4(svCr, svCg, svCb, 1.0f);   // w=1 feeds den
        }
        __syncthreads();

        // ---- Phase 4: accumulate survivors, SPLIT-strided, packed accs ----
        #pragma unroll 2
        for (int i = sub; i < cnt; i += SPLIT) {
            float4 p1 = sP1[i];
            float4 p2 = sP2[i];
            unsigned long long dxy = add2(xyp, px2(p1.x, p1.y)); // (xf-x, yf-y)
            float ddx, ddy; upx2(ddx, ddy, dxy);
            float d2 = fmaf(ddx, ddx, ddy * ddy);
            float e  = exp2f(fmaf(p1.z, d2, p1.w));
            unsigned long long e2 = px2(e, e);
            accRG = fma2(e2, px2(p2.x, p2.y), accRG);
            accBD = fma2(e2, px2(p2.z, p2.w), accBD);
        }
        // no trailing sync: next iteration's post-ballot barrier guards reuse
    }

    // ---- Final: unpack (fixed order), 4-sub combine via reused shared ----
    __syncthreads();
    float4* sAcc = sP1;
    {
        float r, g, bl, d;
        upx2(r, g, accRG);
        upx2(bl, d, accBD);
        sAcc[t] = make_float4(r, g, bl, d);
    }
    __syncthreads();

    if (t < PIX) {
        float4 a0 = sAcc[t];
        float4 a1 = sAcc[t + PIX];
        float4 a2 = sAcc[t + 2 * PIX];
        float4 a3 = sAcc[t + 3 * PIX];
        float r  = (a0.x + a1.x) + (a2.x + a3.x);
        float g  = (a0.y + a1.y) + (a2.y + a3.y);
        float bl = (a0.z + a1.z) + (a2.z + a3.z);
        float d  = (a0.w + a1.w) + (a2.w + a3.w);
        float invd = 1.0f / (d + 1e-8f);
        int px = x0 + (t & (TILE - 1));
        int py = y0 + (t >> 4);
        int o = ((b * 3 + 0) * IMG_H + py) * IMG_W + px;
        out[o]                     = r  * invd;
        out[o + IMG_H * IMG_W]     = g  * invd;
        out[o + 2 * IMG_H * IMG_W] = bl * invd;
    }
}

extern "C" void kernel_launch(void* const* d_in, const int* in_sizes, int n_in,
                              void* d_out, int out_size) {
    const float* positions = (const float*)d_in[0];  // (N,3)
    const float* colors    = (const float*)d_in[1];  // (N,3)
    const float* opacities = (const float*)d_in[2];  // (N,1)
    const float* scales    = (const float*)d_in[3];  // (N,1)
    const float* qvec      = (const float*)d_in[4];  // (B,4)
    const float* tvec      = (const float*)d_in[5];  // (B,3)

    int N = in_sizes[0] / 3;
    int B = in_sizes[4] / 4;

    dim3 grid(IMG_W / TILE, IMG_H / TILE, B);
    fused_kernel<<<grid, NT>>>((float*)d_out, positions, colors, opacities,
                               scales, qvec, tvec, N);
}

// round 14
// speedup vs baseline: 1.1255x; 1.1255x over previous
#include <cuda_runtime.h>
#include <math.h>

// Problem constants (fixed by reference)
#define IMG_W 128
#define IMG_H 128
#define TILE  16              // 16x16 tiles -> 8*8*B = 128 blocks (single wave)
#define PIX   256             // pixels per tile
#define HALF  128             // pixel-pairs per tile (each thread: rows y, y+8)
#define SPLIT 8               // gaussian-axis interleave in accumulate
#define NT    1024            // threads per block
#define CHUNK 1024            // gaussians per chunk (1 per thread)
#define NWARP (NT / 32)       // 32

__device__ __forceinline__ float ex2f(float x) {
    float r;
    asm("ex2.approx.f32 %0, %1;" : "=f"(r) : "f"(x));
    return r;
}
__device__ __forceinline__ float lg2f(float x) {
    float r;
    asm("lg2.approx.f32 %0, %1;" : "=f"(r) : "f"(x));
    return r;
}

// Fully fused, pipelined, scalar phase 4 with 2 pixels per thread.
__global__ void __launch_bounds__(NT)
fused_kernel(float* __restrict__ out,
             const float* __restrict__ pos,
             const float* __restrict__ col,
             const float* __restrict__ opa,
             const float* __restrict__ sca,
             const float* __restrict__ qv,
             const float* __restrict__ tv,
             int N) {
    // Single buffer: survivor tables during chunks, accumulator table at the end.
    __shared__ float4 sBuf[2 * CHUNK];            // 32 KB
    __shared__ int    sWCnt[NWARP];
    float4* sP1 = sBuf;                           // {projx, projy, K2, lo}
    float4* sP2 = sBuf + CHUNK;                   // {r, g, b, 1}

    const int t    = threadIdx.x;
    const int lane = t & 31;
    const int wid  = t >> 5;            // 0..31
    const int sub  = t >> 7;            // 0..7 (constant within each warp)
    const int half = t & (HALF - 1);    // pixel-pair id 0..127
    const int b    = blockIdx.z;
    const int x0   = blockIdx.x * TILE;
    const int y0   = blockIdx.y * TILE;
    const float xf  = (float)(x0 + (half & (TILE - 1)));
    const float yfA = (float)(y0 + (half >> 4));        // rows 0..7
    const float yfB = yfA + 8.0f;                       // rows 8..15

    const float fx0 = (float)x0, fx1 = (float)(x0 + TILE - 1);
    const float fy0 = (float)y0, fy1 = (float)(y0 + TILE - 1);

    // Camera; fold projection constants into rows: proj = (A·p + At) / (R2·p + tz)
    float qw = qv[b * 4 + 0], qx = qv[b * 4 + 1], qy = qv[b * 4 + 2], qz = qv[b * 4 + 3];
    float inv = rsqrtf(qw * qw + qx * qx + qy * qy + qz * qz);
    qw *= inv; qx *= inv; qy *= inv; qz *= inv;
    const float R00 = 1.f - 2.f * (qy * qy + qz * qz), R01 = 2.f * (qx * qy - qz * qw), R02 = 2.f * (qx * qz + qy * qw);
    const float R10 = 2.f * (qx * qy + qz * qw), R11 = 1.f - 2.f * (qx * qx + qz * qz), R12 = 2.f * (qy * qz - qx * qw);
    const float R20 = 2.f * (qx * qz - qy * qw), R21 = 2.f * (qy * qz + qx * qw), R22 = 1.f - 2.f * (qx * qx + qy * qy);
    const float tx = tv[b * 3 + 0], ty = tv[b * 3 + 1], tz = tv[b * 3 + 2];
    const float A00 = fmaf(500.f, R00, 64.f * R20), A01 = fmaf(500.f, R01, 64.f * R21), A02 = fmaf(500.f, R02, 64.f * R22);
    const float A10 = fmaf(500.f, R10, 64.f * R20), A11 = fmaf(500.f, R11, 64.f * R21), A12 = fmaf(500.f, R12, 64.f * R22);
    const float Atx = fmaf(500.f, tx, 64.f * tz),   Aty = fmaf(500.f, ty, 64.f * tz);

    float aRA = 0.f, aGA = 0.f, aBA = 0.f, aDA = 0.f;   // pixel A accumulators
    float aRB = 0.f, aGB = 0.f, aBB = 0.f, aDB = 0.f;   // pixel B accumulators

    // ---- Prologue: prefetch chunk 0 pos/sca (4 independent LDGs) ----
    float cPx = 0.f, cPy = 0.f, cPz = 0.f, cSc = 1.f;
    if (t < N) {
        cPx = pos[t * 3 + 0]; cPy = pos[t * 3 + 1]; cPz = pos[t * 3 + 2];
        cSc = sca[t];
    }

    for (int base = 0; base < N; base += CHUNK) {
        const int g = base + t;
        const bool valid = g < N;

        // ---- Phase 1: project + conservative cull (lo <= 0 bound) ----
        float czm = R20 * cPx + R21 * cPy + R22 * cPz + tz;
        float iz  = __fdividef(1.0f, czm);
        float projx = (A00 * cPx + A01 * cPy + A02 * cPz + Atx) * iz;
        float projy = (A10 * cPx + A11 * cPy + A12 * cPz + Aty) * iz;
        float K2 = __fdividef(-0.72134752044f, cSc * cSc);   // -1/(2 var ln2)

        float dx = fmaxf(0.f, fmaxf(fx0 - projx, projx - fx1));
        float dy = fmaxf(0.f, fmaxf(fy0 - projy, projy - fy1));
        float amax = K2 * fmaf(dx, dx, dy * dy);
        bool keepIt = valid && (amax > -60.f);               // NaN fails -> culled

        // ---- Prefetch next chunk pos/sca (drains behind compaction/accumulate) ----
        {
            int gn = base + CHUNK + t;
            if (gn < N) {
                cPx = pos[gn * 3 + 0]; cPy = pos[gn * 3 + 1]; cPz = pos[gn * 3 + 2];
                cSc = sca[gn];
            }
        }

        // ---- Phase 2: ballot; counts; barrier doubles as smem-reuse guard ----
        unsigned m = __ballot_sync(0xffffffffu, keepIt);
        int myOff = __popc(m & ((1u << lane) - 1u));
        if (lane == 0) sWCnt[wid] = __popc(m);
        __syncthreads();

        // ---- Phase 3: redundant all-warp scan; survivors fetch opa/col here ----
        int cvec = sWCnt[lane];
        int incl = cvec;
        #pragma unroll
        for (int o = 1; o < 32; o <<= 1) {
            int v = __shfl_up_sync(0xffffffffu, incl, o);
            if (lane >= o) incl += v;
        }
        int warpBase = __shfl_sync(0xffffffffu, incl - cvec, wid);
        int cnt      = __shfl_sync(0xffffffffu, incl, 31);

        if (keepIt) {
            int wpos = warpBase + myOff;
            float lo = lg2f(fmaxf(opa[g], 1e-30f));          // folded opacity
            sP1[wpos] = make_float4(projx, projy, K2, lo);
            sP2[wpos] = make_float4(col[g * 3 + 0], col[g * 3 + 1], col[g * 3 + 2], 1.0f);
        }
        __syncthreads();

        // ---- Phase 4: accumulate; 2 pixels share LDS + dx work ----
        #pragma unroll 2
        for (int i = sub; i < cnt; i += SPLIT) {
            float4 p1 = sP1[i];
            float4 p2 = sP2[i];
            float ddx  = xf - p1.x;
            float argx = fmaf(p1.z, ddx * ddx, p1.w);        // K2*dx^2 + lo

            float dyA  = yfA - p1.y;
            float eA   = ex2f(fmaf(p1.z * dyA, dyA, argx));
            aDA += eA;
            aRA = fmaf(eA, p2.x, aRA);
            aGA = fmaf(eA, p2.y, aGA);
            aBA = fmaf(eA, p2.z, aBA);

            float dyB  = yfB - p1.y;
            float eB   = ex2f(fmaf(p1.z * dyB, dyB, argx));
            aDB += eB;
            aRB = fmaf(eB, p2.x, aRB);
            aGB = fmaf(eB, p2.y, aGB);
            aBB = fmaf(eB, p2.z, aBB);
        }
        // no trailing sync: next iteration's post-ballot barrier guards reuse
    }

    // ---- Final: 8-sub fixed-order combine via reused shared ----
    __syncthreads();
    float4* sAcc = sBuf;                 // 2048 entries: [sub][pixel]
    sAcc[sub * PIX + half]        = make_float4(aRA, aGA, aBA, aDA);
    sAcc[sub * PIX + half + HALF] = make_float4(aRB, aGB, aBB, aDB);
    __syncthreads();

    if (t < PIX) {
        float r = 0.f, g = 0.f, bl = 0.f, d = 0.f;
        #pragma unroll
        for (int s = 0; s < SPLIT; ++s) {
            float4 a = sAcc[s * PIX + t];
            r += a.x; g += a.y; bl += a.z; d += a.w;
        }
        float invd = 1.0f / (d + 1e-8f);
        int px = x0 + (t & (TILE - 1));
        int py = y0 + (t >> 4);
        int o = ((b * 3 + 0) * IMG_H + py) * IMG_W + px;
        out[o]                     = r  * invd;
        out[o + IMG_H * IMG_W]     = g  * invd;
        out[o + 2 * IMG_H * IMG_W] = bl * invd;
    }
}

extern "C" void kernel_launch(void* const* d_in, const int* in_sizes, int n_in,
                              void* d_out, int out_size) {
    const float* positions = (const float*)d_in[0];  // (N,3)
    const float* colors    = (const float*)d_in[1];  // (N,3)
    const float* opacities = (const float*)d_in[2];  // (N,1)
    const float* scales    = (const float*)d_in[3];  // (N,1)
    const float* qvec      = (const float*)d_in[4];  // (B,4)
    const float* tvec      = (const float*)d_in[5];  // (B,3)

    int N = in_sizes[0] / 3;
    int B = in_sizes[4] / 4;

    dim3 grid(IMG_W / TILE, IMG_H / TILE, B);
    fused_kernel<<<grid, NT>>>((float*)d_out, positions, colors, opacities,
                               scales, qvec, tvec, N);
}